// round 11
// baseline (speedup 1.0000x reference)
#include <cuda_runtime.h>

#define SEQ 2048
#define BB  64
#define IND 512
#define HH  512
#define NCTA 128
#define NTHR_PRE  256
#define NTHR_SCAN 512

typedef unsigned long long ull;

// ---------------- global scratch (static device memory: allowed) ----------------
// gx layout: [t][group(8)][cta(16)] blocks of 8 rows x 96 cols
// (cols 0-31 z-pre, 32-63 r-pre, 64-95 cand-pre), biases folded. Block = 768 floats.
__device__ float g_gx[(size_t)SEQ * 8 * 16 * 768];
__device__ float g_h[BB * HH];        // current hidden state
__device__ float g_rh[BB * HH];       // r * h_prev
__device__ unsigned g_ctr[16 * 32];   // 16 barrier counters, padded to 128B lines

// ---------------- helpers ----------------
__device__ __forceinline__ ull ffma2(ull a, ull b, ull c) {
    ull d;
    asm("fma.rn.f32x2 %0, %1, %2, %3;" : "=l"(d) : "l"(a), "l"(b), "l"(c));
    return d;
}
__device__ __forceinline__ float ull_sum(ull v) {
    return __uint_as_float((unsigned)(v & 0xffffffffULL)) +
           __uint_as_float((unsigned)(v >> 32));
}
__device__ __forceinline__ float sigmoidf_(float x) {
    return 1.0f / (1.0f + __expf(-x));
}
__device__ __forceinline__ float tanhf_(float x) {
    return 1.0f - 2.0f / (__expf(2.0f * x) + 1.0f);
}
__device__ __forceinline__ void bar_arrive(unsigned* ctr) {
    __syncthreads();
    if (threadIdx.x == 0)
        asm volatile("red.release.gpu.global.add.u32 [%0], %1;"
                     :: "l"(ctr), "r"(1u) : "memory");
}
__device__ __forceinline__ void bar_wait(unsigned* ctr, unsigned goal) {
    if (threadIdx.x == 0) {
        unsigned v;
        do {
            asm volatile("ld.acquire.gpu.u32 %0, [%1];" : "=r"(v) : "l"(ctr) : "memory");
        } while (v < goal);
    }
    __syncthreads();
}

// ---------------- precompute: gx = x @ [Wg_x | Wc_x] + [bg | bc], remapped ----
__global__ void __launch_bounds__(NTHR_PRE) precompute_kernel(
    const float* __restrict__ x, const float* __restrict__ Wg,
    const float* __restrict__ bg, const float* __restrict__ Wc,
    const float* __restrict__ bc, const float* __restrict__ h0)
{
    __shared__ float2 as2[8 * 128];
    __shared__ float2 bs2[8 * 64];

    const int tid = threadIdx.x;

    if (blockIdx.x == 0 && blockIdx.y == 0) {
        for (int i = tid; i < BB * HH; i += NTHR_PRE) g_h[i] = h0[i];
        if (tid < 16) g_ctr[tid * 32] = 0u;
    }

    const int bx = blockIdx.x;          // 0..11 (8 Wg tiles, 4 Wc tiles)
    const int m0 = blockIdx.y * 128;

    const float* Wp; const float* bias; int ldw, n0;
    if (bx < 8) { Wp = Wg; bias = bg; ldw = 1024; n0 = bx * 128; }
    else        { Wp = Wc; bias = bc; ldw = 512;  n0 = (bx - 8) * 128; }

    const int tx = tid & 15, ty = tid >> 4;
    const int arow = tid >> 1, acol = (tid & 1) * 4;
    const int bkrow = tid >> 5, bcol2 = (tid & 31) * 2;

    const float* aptr = x + (size_t)(m0 + arow) * IND + acol;
    const float* bptr = Wp + (size_t)bkrow * ldw + n0 + bcol2 * 2;

    float4 areg = *(const float4*)aptr;
    float4 breg = *(const float4*)bptr;

    ull acc[8][4];
#pragma unroll
    for (int i = 0; i < 8; ++i)
#pragma unroll
        for (int j = 0; j < 4; ++j) acc[i][j] = 0ULL;

    for (int kt = 0; kt < IND / 8; ++kt) {
        as2[(acol + 0) * 128 + arow] = make_float2(areg.x, areg.x);
        as2[(acol + 1) * 128 + arow] = make_float2(areg.y, areg.y);
        as2[(acol + 2) * 128 + arow] = make_float2(areg.z, areg.z);
        as2[(acol + 3) * 128 + arow] = make_float2(areg.w, areg.w);
        *(float4*)&bs2[bkrow * 64 + bcol2] = breg;
        __syncthreads();
        if (kt + 1 < IND / 8) {
            areg = *(const float4*)(aptr + (kt + 1) * 8);
            breg = *(const float4*)(bptr + (size_t)(kt + 1) * 8 * ldw);
        }
#pragma unroll
        for (int k = 0; k < 8; ++k) {
            ulonglong2 a01 = *(const ulonglong2*)&as2[k * 128 + ty * 8];
            ulonglong2 a23 = *(const ulonglong2*)&as2[k * 128 + ty * 8 + 2];
            ulonglong2 a45 = *(const ulonglong2*)&as2[k * 128 + ty * 8 + 4];
            ulonglong2 a67 = *(const ulonglong2*)&as2[k * 128 + ty * 8 + 6];
            ulonglong2 b01 = *(const ulonglong2*)&bs2[k * 64 + tx * 4];
            ulonglong2 b23 = *(const ulonglong2*)&bs2[k * 64 + tx * 4 + 2];
            ull av[8] = {a01.x, a01.y, a23.x, a23.y, a45.x, a45.y, a67.x, a67.y};
            ull bv[4] = {b01.x, b01.y, b23.x, b23.y};
#pragma unroll
            for (int i = 0; i < 8; ++i)
#pragma unroll
                for (int j = 0; j < 4; ++j)
                    acc[i][j] = ffma2(av[i], bv[j], acc[i][j]);
        }
        __syncthreads();
    }

    float bvl[8];
#pragma unroll
    for (int j = 0; j < 8; ++j) bvl[j] = bias[n0 + tx * 8 + j];

    // Destination remap: (bx, tx) -> (cta, slot)
    int cta, slot;
    if (bx < 8) {
        int gcol = bx * 128 + tx * 8;
        if (gcol < 512) { cta = gcol >> 5; slot = gcol & 31; }
        else { int rc = gcol - 512; cta = rc >> 5; slot = 32 + (rc & 31); }
    } else {
        int ccol = (bx - 8) * 128 + tx * 8;
        cta = ccol >> 5; slot = 64 + (ccol & 31);
    }

#pragma unroll
    for (int i = 0; i < 8; ++i) {
        int m = m0 + ty * 8 + i;
        int t = m >> 6, b = m & 63, g = b >> 3, r = b & 7;
        float* op = g_gx + (((size_t)t * 8 + g) * 16 + cta) * 768 + r * 96 + slot;
        float2 c0, c1, c2, c3;
        c0.x = __uint_as_float((unsigned)acc[i][0]); c0.y = __uint_as_float((unsigned)(acc[i][0] >> 32));
        c1.x = __uint_as_float((unsigned)acc[i][1]); c1.y = __uint_as_float((unsigned)(acc[i][1] >> 32));
        c2.x = __uint_as_float((unsigned)acc[i][2]); c2.y = __uint_as_float((unsigned)(acc[i][2] >> 32));
        c3.x = __uint_as_float((unsigned)acc[i][3]); c3.y = __uint_as_float((unsigned)(acc[i][3] >> 32));
        *(float4*)(op)     = make_float4(c0.x + bvl[0], c0.y + bvl[1],
                                         c1.x + bvl[2], c1.y + bvl[3]);
        *(float4*)(op + 4) = make_float4(c2.x + bvl[4], c2.y + bvl[5],
                                         c3.x + bvl[6], c3.y + bvl[7]);
    }
}

// ---------------- scan kernel building blocks ----------------
// All GEMMs: 8 rows x 32 cols x 512 k. 16 warps; warp ks owns k-slice [ks*32,+32).
// Lane = (rg2 = ln>>3, cg2 = ln&7); thread tile 2 rows x 4 cols, 8 k-chunk iters.
// Partials: P[(ks*8 + i*4 + j)*32 + ln], 16*8*32 = 4096 entries.
__device__ __forceinline__ void gemm16(const float* __restrict__ hb,
                                       const float* __restrict__ wb,
                                       float* __restrict__ Pout,
                                       int ks, int ln, int rg2, int cg2)
{
    ull acc[2][4];
#pragma unroll
    for (int i = 0; i < 2; ++i)
#pragma unroll
        for (int j = 0; j < 4; ++j) acc[i][j] = 0ULL;

    const int kc0 = ks * 8;
#pragma unroll
    for (int tt = 0; tt < 8; ++tt) {
        int kc = kc0 + tt;
        ulonglong2 hv[2], wv[4];
#pragma unroll
        for (int i = 0; i < 2; ++i) {
            int row = rg2 * 2 + i;                 // 0..7
            hv[i] = *(const ulonglong2*)&hb[row * 512 + ((kc ^ row) << 2)];
        }
#pragma unroll
        for (int j = 0; j < 4; ++j) {
            int c = cg2 * 4 + j;                   // swizzle key (c>>2)&7 == cg2
            wv[j] = *(const ulonglong2*)&wb[c * 512 + ((kc ^ cg2) << 2)];
        }
#pragma unroll
        for (int i = 0; i < 2; ++i)
#pragma unroll
            for (int j = 0; j < 4; ++j) {
                acc[i][j] = ffma2(hv[i].x, wv[j].x, acc[i][j]);
                acc[i][j] = ffma2(hv[i].y, wv[j].y, acc[i][j]);
            }
    }
#pragma unroll
    for (int i = 0; i < 2; ++i)
#pragma unroll
        for (int j = 0; j < 4; ++j)
            Pout[(ks * 8 + i * 4 + j) * 32 + ln] = ull_sum(acc[i][j]);
}

// Per-warp staging: warp ks loads its own k-slice (8 rows x 32 k = 1 KB).
__device__ __forceinline__ void stage_slice(float* __restrict__ hst,
                                            const float* __restrict__ src,
                                            int r0, int ks, int ln)
{
#pragma unroll
    for (int i = 0; i < 2; ++i) {
        int idx = i * 32 + ln;                    // 0..63
        int row = idx >> 3;                       // 0..7
        int kc  = ks * 8 + (idx & 7);
        float4 v = __ldcg((const float4*)(src + (size_t)(r0 + row) * HH + kc * 4));
        *(float4*)&hst[row * 512 + ((kc ^ row) << 2)] = v;
    }
}

// ---------------- persistent scan kernel ----------------
// 128 CTAs x 512 thr, 1/SM. Group g = bid>>4 owns batch rows [g*8, +8).
// cid = bid&15: z cols [cid*32,+32), r cols [512+cid*32,+32), cand cols [cid*32,+32).
// Step: stage h -> r-GEMM -> rh out + arrive A -> z-GEMM (hides A) -> wait A
//       -> stage rh -> cand-GEMM -> h update + arrive B -> out store -> wait B.
// P is a single buffer reused r -> z -> cand (bar_arrive/bar_wait syncthreads
// separate the reuse windows).
// smem (floats): wg 32x512 z | 32x512 r | wc 32x512 | hst 8x512 | P 4096
#define SM_WG  0
#define SM_WC  32768
#define SM_HST 49152
#define SM_P   53248
#define SMEM_FLOATS 57344
#define SMEM_BYTES (SMEM_FLOATS * 4)

__global__ void __launch_bounds__(NTHR_SCAN, 1) scan_kernel(
    const float* __restrict__ Wg, const float* __restrict__ Wc,
    float* __restrict__ out, int write_outputs, int write_hlast)
{
    extern __shared__ float sm[];
    float* wg  = sm + SM_WG;           // cols 0-31 = z, 32-63 = r
    float* wc  = sm + SM_WC;
    float* hst = sm + SM_HST;
    float* P   = sm + SM_P;

    const int tid = threadIdx.x;
    const int g   = blockIdx.x >> 4;
    const int cid = blockIdx.x & 15;
    const int r0  = g * 8;
    const int c32 = cid * 32;

    // ---- load recurrent weight slabs once (swizzled, k-contiguous per col) ----
    for (int idx = tid; idx < 64 * 512; idx += NTHR_SCAN) {
        int k = idx >> 6, c = idx & 63;
        int gc = (c < 32) ? (c32 + c) : (512 + c32 + (c - 32));
        float v = Wg[(size_t)(512 + k) * 1024 + gc];
        wg[c * 512 + (((k >> 2) ^ ((c >> 2) & 7)) << 2) + (k & 3)] = v;
    }
    for (int idx = tid; idx < 32 * 512; idx += NTHR_SCAN) {
        int k = idx >> 5, c = idx & 31;
        float v = Wc[(size_t)(512 + k) * 512 + c32 + c];
        wc[c * 512 + (((k >> 2) ^ ((c >> 2) & 7)) << 2) + (k & 3)] = v;
    }
    __syncthreads();

    const int ks  = tid >> 5;          // 0..15 (k-slice warp)
    const int ln  = tid & 31;
    const int rg2 = ln >> 3, cg2 = ln & 7;

    // reduce/epilogue ownership: first 8 warps (tid < 256), v = tid>>5 in 0..7
    const bool owner = (tid < 256);
    const int v2   = ks & 7;
    const int row2 = rg2 * 2 + (v2 >> 2);
    const int col2 = cg2 * 4 + (v2 & 3);
    const int jj2  = c32 + col2;
    const int b2   = r0 + row2;

    unsigned* ctrA = g_ctr + (g * 2) * 32;
    unsigned* ctrB = g_ctr + (g * 2 + 1) * 32;

    // h_prev for this owner's element, carried in a register across steps
    float hprev = owner ? __ldcg(g_h + (size_t)b2 * HH + jj2) : 0.f;

    for (int t = 0; t < SEQ; ++t) {
        // prefetch pre-activations (DRAM; consumed >=1k cyc later)
        const float* gblk = g_gx + (((size_t)t * 8 + g) * 16 + cid) * 768;
        float gxz = 0.f, gxr = 0.f, gxc = 0.f;
        if (owner) {
            gxz = __ldcg(gblk + row2 * 96 + col2);
            gxr = __ldcg(gblk + row2 * 96 + 32 + col2);
            gxc = __ldcg(gblk + row2 * 96 + 64 + col2);
        }

        // ---- per-warp stage h slice, straight into r-GEMM ----
        stage_slice(hst, g_h, r0, ks, ln);
        __syncwarp();
        gemm16(hst, wg + 32 * 512, P, ks, ln, rg2, cg2);     // r
        __syncthreads();

        // ---- r reduce + rh out ----
        if (owner) {
            float s = 0.f;
#pragma unroll
            for (int q = 0; q < 16; ++q) s += P[(q * 8 + v2) * 32 + ln];
            float r = sigmoidf_(s + gxr);
            __stcg(g_rh + (size_t)b2 * HH + jj2, r * hprev);
        }
        bar_arrive(ctrA);   // syncthreads (frees P for z) + release-add

        // ---- z-GEMM overlaps barrier A propagation ----
        gemm16(hst, wg, P, ks, ln, rg2, cg2);                // z
        __syncthreads();
        float z = 0.f;
        if (owner) {
            float s = 0.f;
#pragma unroll
            for (int q = 0; q < 16; ++q) s += P[(q * 8 + v2) * 32 + ln];
            z = sigmoidf_(s + gxz);
        }

        bar_wait(ctrA, (unsigned)(t + 1) * 16u);  // ends with syncthreads (frees P)

        // ---- per-warp stage rh slice, straight into cand-GEMM ----
        stage_slice(hst, g_rh, r0, ks, ln);
        __syncwarp();
        gemm16(hst, wc, P, ks, ln, rg2, cg2);                // cand
        __syncthreads();

        // ---- cand reduce + h update ----
        float hn = 0.f;
        if (owner) {
            float s = 0.f;
#pragma unroll
            for (int q = 0; q < 16; ++q) s += P[(q * 8 + v2) * 32 + ln];
            float cand = tanhf_(s + gxc);
            hn = fmaf(z, cand - hprev, hprev);   // (1-z)*h + z*cand
            __stcg(g_h + (size_t)b2 * HH + jj2, hn);
        }

        bar_arrive(ctrB);

        // out stores after the release — not on the fence's drain path
        if (owner) {
            if (write_outputs)
                __stcs(out + ((size_t)t * BB + b2) * HH + jj2, hn);
            if (write_hlast && t == SEQ - 1) {
                size_t off = write_outputs ? (size_t)SEQ * BB * HH : 0;
                out[off + (size_t)b2 * HH + jj2] = hn;
            }
            hprev = hn;                          // carry for next step
        }

        bar_wait(ctrB, (unsigned)(t + 1) * 16u);
    }
}

// ---------------- launch ----------------
extern "C" void kernel_launch(void* const* d_in, const int* in_sizes, int n_in,
                              void* d_out, int out_size) {
    const float* x  = (const float*)d_in[0];
    const float* h0 = (const float*)d_in[1];
    const float* Wg = (const float*)d_in[2];
    const float* bg = (const float*)d_in[3];
    const float* Wc = (const float*)d_in[4];
    const float* bc = (const float*)d_in[5];
    float* out = (float*)d_out;

    cudaFuncSetAttribute(scan_kernel, cudaFuncAttributeMaxDynamicSharedMemorySize,
                         SMEM_BYTES);

    long long full = (long long)SEQ * BB * HH;
    int write_outputs = (out_size >= full) ? 1 : 0;
    long long hlast_off = write_outputs ? full : 0;
    int write_hlast = (out_size >= hlast_off + BB * HH) ? 1 : 0;

    dim3 pgrid(12, 1024);
    precompute_kernel<<<pgrid, NTHR_PRE>>>(x, Wg, bg, Wc, bc, h0);
    scan_kernel<<<NCTA, NTHR_SCAN, SMEM_BYTES>>>(Wg, Wc, out, write_outputs, write_hlast);
}

// round 13
// speedup vs baseline: 1.0003x; 1.0003x over previous
#include <cuda_runtime.h>

#define SEQ 2048
#define BB  64
#define IND 512
#define HH  512
#define NCTA 128
#define NTHR_PRE  256
#define NTHR_SCAN 512

typedef unsigned long long ull;

// ---------------- global scratch (static device memory: allowed) ----------------
// gx layout: [t][group(8)][cta(16)] blocks of 8 rows x 96 cols
// (cols 0-31 z-pre, 32-63 r-pre, 64-95 cand-pre), biases folded. Block = 768 floats.
__device__ float g_gx[(size_t)SEQ * 8 * 16 * 768];
__device__ float g_h[BB * HH];        // current hidden state
__device__ float g_rh[BB * HH];       // r * h_prev
__device__ unsigned g_ctr[16 * 32];   // 16 barrier counters, padded to 128B lines

// ---------------- helpers ----------------
__device__ __forceinline__ ull ffma2(ull a, ull b, ull c) {
    ull d;
    asm("fma.rn.f32x2 %0, %1, %2, %3;" : "=l"(d) : "l"(a), "l"(b), "l"(c));
    return d;
}
__device__ __forceinline__ float ull_sum(ull v) {
    return __uint_as_float((unsigned)(v & 0xffffffffULL)) +
           __uint_as_float((unsigned)(v >> 32));
}
__device__ __forceinline__ float sigmoidf_(float x) {
    return 1.0f / (1.0f + __expf(-x));
}
__device__ __forceinline__ float tanhf_(float x) {
    return 1.0f - 2.0f / (__expf(2.0f * x) + 1.0f);
}
__device__ __forceinline__ void bar_arrive(unsigned* ctr) {
    __syncthreads();
    if (threadIdx.x == 0)
        asm volatile("red.release.gpu.global.add.u32 [%0], %1;"
                     :: "l"(ctr), "r"(1u) : "memory");
}
__device__ __forceinline__ void bar_wait(unsigned* ctr, unsigned goal) {
    if (threadIdx.x == 0) {
        unsigned v;
        do {
            asm volatile("ld.acquire.gpu.u32 %0, [%1];" : "=r"(v) : "l"(ctr) : "memory");
        } while (v < goal);
    }
    __syncthreads();
}

// ---------------- precompute: gx = x @ [Wg_x | Wc_x] + [bg | bc], remapped ----
__global__ void __launch_bounds__(NTHR_PRE) precompute_kernel(
    const float* __restrict__ x, const float* __restrict__ Wg,
    const float* __restrict__ bg, const float* __restrict__ Wc,
    const float* __restrict__ bc, const float* __restrict__ h0)
{
    __shared__ float2 as2[8 * 128];
    __shared__ float2 bs2[8 * 64];

    const int tid = threadIdx.x;

    if (blockIdx.x == 0 && blockIdx.y == 0) {
        for (int i = tid; i < BB * HH; i += NTHR_PRE) g_h[i] = h0[i];
        if (tid < 16) g_ctr[tid * 32] = 0u;
    }

    const int bx = blockIdx.x;          // 0..11 (8 Wg tiles, 4 Wc tiles)
    const int m0 = blockIdx.y * 128;

    const float* Wp; const float* bias; int ldw, n0;
    if (bx < 8) { Wp = Wg; bias = bg; ldw = 1024; n0 = bx * 128; }
    else        { Wp = Wc; bias = bc; ldw = 512;  n0 = (bx - 8) * 128; }

    const int tx = tid & 15, ty = tid >> 4;
    const int arow = tid >> 1, acol = (tid & 1) * 4;
    const int bkrow = tid >> 5, bcol2 = (tid & 31) * 2;

    const float* aptr = x + (size_t)(m0 + arow) * IND + acol;
    const float* bptr = Wp + (size_t)bkrow * ldw + n0 + bcol2 * 2;

    float4 areg = *(const float4*)aptr;
    float4 breg = *(const float4*)bptr;

    ull acc[8][4];
#pragma unroll
    for (int i = 0; i < 8; ++i)
#pragma unroll
        for (int j = 0; j < 4; ++j) acc[i][j] = 0ULL;

    for (int kt = 0; kt < IND / 8; ++kt) {
        as2[(acol + 0) * 128 + arow] = make_float2(areg.x, areg.x);
        as2[(acol + 1) * 128 + arow] = make_float2(areg.y, areg.y);
        as2[(acol + 2) * 128 + arow] = make_float2(areg.z, areg.z);
        as2[(acol + 3) * 128 + arow] = make_float2(areg.w, areg.w);
        *(float4*)&bs2[bkrow * 64 + bcol2] = breg;
        __syncthreads();
        if (kt + 1 < IND / 8) {
            areg = *(const float4*)(aptr + (kt + 1) * 8);
            breg = *(const float4*)(bptr + (size_t)(kt + 1) * 8 * ldw);
        }
#pragma unroll
        for (int k = 0; k < 8; ++k) {
            ulonglong2 a01 = *(const ulonglong2*)&as2[k * 128 + ty * 8];
            ulonglong2 a23 = *(const ulonglong2*)&as2[k * 128 + ty * 8 + 2];
            ulonglong2 a45 = *(const ulonglong2*)&as2[k * 128 + ty * 8 + 4];
            ulonglong2 a67 = *(const ulonglong2*)&as2[k * 128 + ty * 8 + 6];
            ulonglong2 b01 = *(const ulonglong2*)&bs2[k * 64 + tx * 4];
            ulonglong2 b23 = *(const ulonglong2*)&bs2[k * 64 + tx * 4 + 2];
            ull av[8] = {a01.x, a01.y, a23.x, a23.y, a45.x, a45.y, a67.x, a67.y};
            ull bv[4] = {b01.x, b01.y, b23.x, b23.y};
#pragma unroll
            for (int i = 0; i < 8; ++i)
#pragma unroll
                for (int j = 0; j < 4; ++j)
                    acc[i][j] = ffma2(av[i], bv[j], acc[i][j]);
        }
        __syncthreads();
    }

    float bvl[8];
#pragma unroll
    for (int j = 0; j < 8; ++j) bvl[j] = bias[n0 + tx * 8 + j];

    // Destination remap: (bx, tx) -> (cta, slot)
    int cta, slot;
    if (bx < 8) {
        int gcol = bx * 128 + tx * 8;
        if (gcol < 512) { cta = gcol >> 5; slot = gcol & 31; }
        else { int rc = gcol - 512; cta = rc >> 5; slot = 32 + (rc & 31); }
    } else {
        int ccol = (bx - 8) * 128 + tx * 8;
        cta = ccol >> 5; slot = 64 + (ccol & 31);
    }

#pragma unroll
    for (int i = 0; i < 8; ++i) {
        int m = m0 + ty * 8 + i;
        int t = m >> 6, b = m & 63, g = b >> 3, r = b & 7;
        float* op = g_gx + (((size_t)t * 8 + g) * 16 + cta) * 768 + r * 96 + slot;
        float2 c0, c1, c2, c3;
        c0.x = __uint_as_float((unsigned)acc[i][0]); c0.y = __uint_as_float((unsigned)(acc[i][0] >> 32));
        c1.x = __uint_as_float((unsigned)acc[i][1]); c1.y = __uint_as_float((unsigned)(acc[i][1] >> 32));
        c2.x = __uint_as_float((unsigned)acc[i][2]); c2.y = __uint_as_float((unsigned)(acc[i][2] >> 32));
        c3.x = __uint_as_float((unsigned)acc[i][3]); c3.y = __uint_as_float((unsigned)(acc[i][3] >> 32));
        *(float4*)(op)     = make_float4(c0.x + bvl[0], c0.y + bvl[1],
                                         c1.x + bvl[2], c1.y + bvl[3]);
        *(float4*)(op + 4) = make_float4(c2.x + bvl[4], c2.y + bvl[5],
                                         c3.x + bvl[6], c3.y + bvl[7]);
    }
}

// ---------------- scan kernel building blocks ----------------
// All GEMMs: 8 rows x 32 cols x 512 k. 16 warps; warp ks owns k-slice [ks*32,+32).
// Lane = (rg2 = ln>>3, cg2 = ln&7); thread tile 2 rows x 4 cols, 8 k-chunk iters.
// Partials: P[(ks*8 + i*4 + j)*32 + ln], 16*8*32 = 4096 entries.
__device__ __forceinline__ void gemm16(const float* __restrict__ hb,
                                       const float* __restrict__ wb,
                                       float* __restrict__ Pout,
                                       int ks, int ln, int rg2, int cg2)
{
    ull acc[2][4];
#pragma unroll
    for (int i = 0; i < 2; ++i)
#pragma unroll
        for (int j = 0; j < 4; ++j) acc[i][j] = 0ULL;

    const int kc0 = ks * 8;
#pragma unroll
    for (int tt = 0; tt < 8; ++tt) {
        int kc = kc0 + tt;
        ulonglong2 hv[2], wv[4];
#pragma unroll
        for (int i = 0; i < 2; ++i) {
            int row = rg2 * 2 + i;                 // 0..7
            hv[i] = *(const ulonglong2*)&hb[row * 512 + ((kc ^ row) << 2)];
        }
#pragma unroll
        for (int j = 0; j < 4; ++j) {
            int c = cg2 * 4 + j;                   // swizzle key (c>>2)&7 == cg2
            wv[j] = *(const ulonglong2*)&wb[c * 512 + ((kc ^ cg2) << 2)];
        }
#pragma unroll
        for (int i = 0; i < 2; ++i)
#pragma unroll
            for (int j = 0; j < 4; ++j) {
                acc[i][j] = ffma2(hv[i].x, wv[j].x, acc[i][j]);
                acc[i][j] = ffma2(hv[i].y, wv[j].y, acc[i][j]);
            }
    }
#pragma unroll
    for (int i = 0; i < 2; ++i)
#pragma unroll
        for (int j = 0; j < 4; ++j)
            Pout[(ks * 8 + i * 4 + j) * 32 + ln] = ull_sum(acc[i][j]);
}

// Per-warp staging: warp ks loads its own k-slice (8 rows x 32 k = 1 KB).
__device__ __forceinline__ void stage_slice(float* __restrict__ hst,
                                            const float* __restrict__ src,
                                            int r0, int ks, int ln)
{
#pragma unroll
    for (int i = 0; i < 2; ++i) {
        int idx = i * 32 + ln;                    // 0..63
        int row = idx >> 3;                       // 0..7
        int kc  = ks * 8 + (idx & 7);
        float4 v = __ldcg((const float4*)(src + (size_t)(r0 + row) * HH + kc * 4));
        *(float4*)&hst[row * 512 + ((kc ^ row) << 2)] = v;
    }
}

// ---------------- persistent scan kernel ----------------
// 128 CTAs x 512 thr, 1/SM. Group g = bid>>4 owns batch rows [g*8, +8).
// cid = bid&15: z cols [cid*32,+32), r cols [512+cid*32,+32), cand cols [cid*32,+32).
// Step: stage h -> r-GEMM -> rh out + arrive A -> z-GEMM (hides A) -> wait A
//       -> stage rh -> cand-GEMM -> h update + arrive B -> out store -> wait B.
// P is a single buffer reused r -> z -> cand (bar_arrive/bar_wait syncthreads
// separate the reuse windows).
// smem (floats): wg 32x512 z | 32x512 r | wc 32x512 | hst 8x512 | P 4096
#define SM_WG  0
#define SM_WC  32768
#define SM_HST 49152
#define SM_P   53248
#define SMEM_FLOATS 57344
#define SMEM_BYTES (SMEM_FLOATS * 4)

__global__ void __launch_bounds__(NTHR_SCAN, 1) scan_kernel(
    const float* __restrict__ Wg, const float* __restrict__ Wc,
    float* __restrict__ out, int write_outputs, int write_hlast)
{
    extern __shared__ float sm[];
    float* wg  = sm + SM_WG;           // cols 0-31 = z, 32-63 = r
    float* wc  = sm + SM_WC;
    float* hst = sm + SM_HST;
    float* P   = sm + SM_P;

    const int tid = threadIdx.x;
    const int g   = blockIdx.x >> 4;
    const int cid = blockIdx.x & 15;
    const int r0  = g * 8;
    const int c32 = cid * 32;

    // ---- load recurrent weight slabs once (swizzled, k-contiguous per col) ----
    for (int idx = tid; idx < 64 * 512; idx += NTHR_SCAN) {
        int k = idx >> 6, c = idx & 63;
        int gc = (c < 32) ? (c32 + c) : (512 + c32 + (c - 32));
        float v = Wg[(size_t)(512 + k) * 1024 + gc];
        wg[c * 512 + (((k >> 2) ^ ((c >> 2) & 7)) << 2) + (k & 3)] = v;
    }
    for (int idx = tid; idx < 32 * 512; idx += NTHR_SCAN) {
        int k = idx >> 5, c = idx & 31;
        float v = Wc[(size_t)(512 + k) * 512 + c32 + c];
        wc[c * 512 + (((k >> 2) ^ ((c >> 2) & 7)) << 2) + (k & 3)] = v;
    }
    __syncthreads();

    const int ks  = tid >> 5;          // 0..15 (k-slice warp)
    const int ln  = tid & 31;
    const int rg2 = ln >> 3, cg2 = ln & 7;

    // reduce/epilogue ownership: first 8 warps (tid < 256), v = tid>>5 in 0..7
    const bool owner = (tid < 256);
    const int v2   = ks & 7;
    const int row2 = rg2 * 2 + (v2 >> 2);
    const int col2 = cg2 * 4 + (v2 & 3);
    const int jj2  = c32 + col2;
    const int b2   = r0 + row2;

    unsigned* ctrA = g_ctr + (g * 2) * 32;
    unsigned* ctrB = g_ctr + (g * 2 + 1) * 32;

    // h_prev for this owner's element, carried in a register across steps
    float hprev = owner ? __ldcg(g_h + (size_t)b2 * HH + jj2) : 0.f;

    for (int t = 0; t < SEQ; ++t) {
        // prefetch pre-activations (DRAM; consumed >=1k cyc later)
        const float* gblk = g_gx + (((size_t)t * 8 + g) * 16 + cid) * 768;
        float gxz = 0.f, gxr = 0.f, gxc = 0.f;
        if (owner) {
            gxz = __ldcg(gblk + row2 * 96 + col2);
            gxr = __ldcg(gblk + row2 * 96 + 32 + col2);
            gxc = __ldcg(gblk + row2 * 96 + 64 + col2);
        }

        // ---- per-warp stage h slice, straight into r-GEMM ----
        stage_slice(hst, g_h, r0, ks, ln);
        __syncwarp();
        gemm16(hst, wg + 32 * 512, P, ks, ln, rg2, cg2);     // r
        __syncthreads();

        // ---- r reduce + rh out ----
        if (owner) {
            float s = 0.f;
#pragma unroll
            for (int q = 0; q < 16; ++q) s += P[(q * 8 + v2) * 32 + ln];
            float r = sigmoidf_(s + gxr);
            __stcg(g_rh + (size_t)b2 * HH + jj2, r * hprev);
        }
        bar_arrive(ctrA);   // syncthreads (frees P for z) + release-add

        // ---- z-GEMM overlaps barrier A propagation ----
        gemm16(hst, wg, P, ks, ln, rg2, cg2);                // z
        __syncthreads();
        float z = 0.f;
        if (owner) {
            float s = 0.f;
#pragma unroll
            for (int q = 0; q < 16; ++q) s += P[(q * 8 + v2) * 32 + ln];
            z = sigmoidf_(s + gxz);
        }

        bar_wait(ctrA, (unsigned)(t + 1) * 16u);  // ends with syncthreads (frees P)

        // ---- per-warp stage rh slice, straight into cand-GEMM ----
        stage_slice(hst, g_rh, r0, ks, ln);
        __syncwarp();
        gemm16(hst, wc, P, ks, ln, rg2, cg2);                // cand
        __syncthreads();

        // ---- cand reduce + h update ----
        float hn = 0.f;
        if (owner) {
            float s = 0.f;
#pragma unroll
            for (int q = 0; q < 16; ++q) s += P[(q * 8 + v2) * 32 + ln];
            float cand = tanhf_(s + gxc);
            hn = fmaf(z, cand - hprev, hprev);   // (1-z)*h + z*cand
            __stcg(g_h + (size_t)b2 * HH + jj2, hn);
        }

        bar_arrive(ctrB);

        // out stores after the release — not on the fence's drain path
        if (owner) {
            if (write_outputs)
                __stcs(out + ((size_t)t * BB + b2) * HH + jj2, hn);
            if (write_hlast && t == SEQ - 1) {
                size_t off = write_outputs ? (size_t)SEQ * BB * HH : 0;
                out[off + (size_t)b2 * HH + jj2] = hn;
            }
            hprev = hn;                          // carry for next step
        }

        bar_wait(ctrB, (unsigned)(t + 1) * 16u);
    }
}

// ---------------- launch ----------------
extern "C" void kernel_launch(void* const* d_in, const int* in_sizes, int n_in,
                              void* d_out, int out_size) {
    const float* x  = (const float*)d_in[0];
    const float* h0 = (const float*)d_in[1];
    const float* Wg = (const float*)d_in[2];
    const float* bg = (const float*)d_in[3];
    const float* Wc = (const float*)d_in[4];
    const float* bc = (const float*)d_in[5];
    float* out = (float*)d_out;

    cudaFuncSetAttribute(scan_kernel, cudaFuncAttributeMaxDynamicSharedMemorySize,
                         SMEM_BYTES);

    long long full = (long long)SEQ * BB * HH;
    int write_outputs = (out_size >= full) ? 1 : 0;
    long long hlast_off = write_outputs ? full : 0;
    int write_hlast = (out_size >= hlast_off + BB * HH) ? 1 : 0;

    dim3 pgrid(12, 1024);
    precompute_kernel<<<pgrid, NTHR_PRE>>>(x, Wg, bg, Wc, bc, h0);
    scan_kernel<<<NCTA, NTHR_SCAN, SMEM_BYTES>>>(Wg, Wc, out, write_outputs, write_hlast);
}